// round 1
// baseline (speedup 1.0000x reference)
#include <cuda_runtime.h>
#include <math.h>

#define N_POINTS 128
#define STEPS    50
#define N_EVENTS 10000
#define DT       2.0f            // MAX_TIME / STEPS = 100/50
#define SQRT_PI_F 1.7724539f     // float32(sqrt(pi))

#define PAIR_TOTAL (N_POINTS * N_POINTS * STEPS)   // 819200 (upper triangle predicated)
#define TOTAL_WORK (PAIR_TOTAL + N_EVENTS)

#define MAIN_BLOCKS 592
#define MAIN_THREADS 256

// Scratch (allocation-free contract: __device__ globals)
__device__ float g_Z[N_POINTS * 2 * (STEPS + 1)];   // [p][d][s], 51 per row
__device__ float g_ts[STEPS + 1];                   // ts[s], s=0..49; slot 50 = times[M-1] (== tf[49])
__device__ int   g_valid[STEPS];
__device__ double        g_acc = 0.0;
__device__ unsigned int  g_count = 0;

__device__ __forceinline__ int idx_of(float t) {
    const float denom = DT + DT * 0.001f;           // matches dt + dt*float32(0.001)
    return (int)floorf(t / denom);
}

// ---------------------------------------------------------------------------
// Kernel 1: 1 block. Cumsum of Z_steps (threads 0..127) and per-step
// first-event times via binary search (threads 128..178).
// ---------------------------------------------------------------------------
__global__ void prep_kernel(const float* __restrict__ data,
                            const float* __restrict__ z0,
                            const float* __restrict__ v0) {
    int tid = threadIdx.x;
    if (tid < N_POINTS) {
        #pragma unroll
        for (int d = 0; d < 2; ++d) {
            float z = z0[tid * 2 + d];
            float*       Zrow = &g_Z[(tid * 2 + d) * (STEPS + 1)];
            const float* vrow = &v0[(tid * 2 + d) * STEPS];
            Zrow[0] = z;
            float cum = 0.0f;
            #pragma unroll
            for (int s = 0; s < STEPS; ++s) {
                cum += z + vrow[s] * DT;   // Z_steps[s+1] = sum_{k<=s}(z0 + v0[k]*dt)
                Zrow[s + 1] = cum;
            }
        }
    } else if (tid >= 128 && tid <= 128 + STEPS) {
        int s = tid - 128;
        float tlast = data[(N_EVENTS - 1) * 3 + 2];
        if (s == STEPS) {
            g_ts[STEPS] = tlast;                     // tf[49] = times[-1]
        } else {
            // first m with idx_of(times[m]) >= s  (idx monotone since times sorted)
            int lo = 0, hi = N_EVENTS;
            while (lo < hi) {
                int mid = (lo + hi) >> 1;
                if (idx_of(data[mid * 3 + 2]) >= s) hi = mid; else lo = mid + 1;
            }
            int valid = (lo < N_EVENTS) && (idx_of(data[lo * 3 + 2]) == s);
            // segment_min empty -> INT_MAX -> safe = M-1 -> ts = times[M-1]
            g_ts[s]    = valid ? data[lo * 3 + 2] : tlast;
            g_valid[s] = valid;
        }
    }
}

// ---------------------------------------------------------------------------
// Kernel 2: grid-stride over pair terms + event terms; double block-reduce;
// last block writes scalar and resets accumulators (graph-replay safe).
// ---------------------------------------------------------------------------
__global__ void __launch_bounds__(MAIN_THREADS)
main_kernel(const float* __restrict__ data,
            const float* __restrict__ beta,
            const float* __restrict__ v0,
            float* __restrict__ out) {
    const float b0 = beta[0];
    double local = 0.0;

    const int stride = gridDim.x * blockDim.x;
    for (int q = blockIdx.x * blockDim.x + threadIdx.x; q < TOTAL_WORK; q += stride) {
        if (q < PAIR_TOTAL) {
            int s  = q % STEPS;
            int ij = q / STEPS;
            int j  = ij & (N_POINTS - 1);
            int i  = ij >> 7;
            if (i >= j) continue;                    // triu(k=1)
            const float* Zi = &g_Z[(i * 2) * (STEPS + 1)];
            const float* Zj = &g_Z[(j * 2) * (STEPS + 1)];
            const float* vi = &v0[i * 2 * STEPS];
            const float* vj = &v0[j * 2 * STEPS];
            float dzx = Zi[s] - Zj[s];
            float dzy = Zi[STEPS + 1 + s] - Zj[STEPS + 1 + s];
            float dvx = vi[s] - vj[s];
            float dvy = vi[STEPS + s] - vj[STEPS + s];

            float a = fmaxf(dvx * dvx + dvy * dvy, 1e-10f);
            float b = 2.0f * (dzx * dvx + dzy * dvy);
            float c = dzx * dzx + dzy * dzy;
            float sa    = sqrtf(a);
            float shift = b / (2.0f * sa);
            float pref  = (SQRT_PI_F / (2.0f * sa)) * expf(b0 - c + shift * shift);
            float ts = g_ts[s];
            float tf = g_ts[s + 1];
            float integ = pref * (erff(sa * tf + shift) - erff(sa * ts + shift));
            if (g_valid[s]) local -= (double)integ;  // result = events - non_events
        } else {
            int e = q - PAIR_TOTAL;
            float si = data[e * 3 + 0];
            float dj = data[e * 3 + 1];
            float t  = data[e * 3 + 2];
            int i = (int)floorf(si);
            int j = (int)floorf(dj);
            const float denom = DT + DT * 0.001f;
            float stepf = floorf(t / denom);
            int   idx   = (int)stepf;
            float delta = t - stepf * DT;

            const float* Zi = &g_Z[(i * 2) * (STEPS + 1)];
            const float* Zj = &g_Z[(j * 2) * (STEPS + 1)];
            const float* vi = &v0[i * 2 * STEPS];
            const float* vj = &v0[j * 2 * STEPS];
            float zix = Zi[idx]             + vi[idx]         * delta;
            float ziy = Zi[STEPS + 1 + idx] + vi[STEPS + idx] * delta;
            float zjx = Zj[idx]             + vj[idx]         * delta;
            float zjy = Zj[STEPS + 1 + idx] + vj[STEPS + idx] * delta;
            float dx = zix - zjx, dy = ziy - zjy;
            local += (double)(b0 - (dx * dx + dy * dy));
        }
    }

    // block reduction (double)
    __shared__ double sh[MAIN_THREADS];
    sh[threadIdx.x] = local;
    __syncthreads();
    #pragma unroll
    for (int off = MAIN_THREADS / 2; off > 0; off >>= 1) {
        if (threadIdx.x < off) sh[threadIdx.x] += sh[threadIdx.x + off];
        __syncthreads();
    }
    if (threadIdx.x == 0) {
        atomicAdd(&g_acc, sh[0]);
        __threadfence();
        unsigned int old = atomicAdd(&g_count, 1u);
        if (old == gridDim.x - 1) {
            double total = atomicAdd(&g_acc, 0.0);   // coherent read of full sum
            out[0] = (float)total;
            g_acc   = 0.0;                           // reset for next graph replay
            g_count = 0u;
        }
    }
}

// ---------------------------------------------------------------------------
// Inputs (metadata order): data[30000], t0[1], tn[1], beta[1], z0[256], v0[12800]
// Output: float32 scalar.
// ---------------------------------------------------------------------------
extern "C" void kernel_launch(void* const* d_in, const int* in_sizes, int n_in,
                              void* d_out, int out_size) {
    const float* data = (const float*)d_in[0];
    const float* beta = (const float*)d_in[3];
    const float* z0   = (const float*)d_in[4];
    const float* v0   = (const float*)d_in[5];
    float* out = (float*)d_out;

    prep_kernel<<<1, 256>>>(data, z0, v0);
    main_kernel<<<MAIN_BLOCKS, MAIN_THREADS>>>(data, beta, v0, out);
}